// round 10
// baseline (speedup 1.0000x reference)
#include <cuda_runtime.h>
#include <cstdint>

// Problem constants
#define BATCH   4
#define SEQ     4096
#define DMODEL  2048
#define TOKENS  (BATCH * SEQ)     // 16384
#define NCPAD   36                // 16 q + 16 k + w + 3 pad (float4-aligned pitch)
#define DSPLIT  8
#define DCHUNK  (DMODEL / DSPLIT) // 256

typedef unsigned long long u64;

// Scratch (static device globals: no dynamic allocation allowed)
__device__ float g_part[(size_t)DSPLIT * TOKENS * NCPAD];   // ~18.9 MB
__device__ float g_q[TOKENS * 16];
__device__ float g_k[TOKENS * 16];
__device__ float g_w[TOKENS];

// ---- packed f32x2 helpers (FFMA2 path, PTX-only on sm_103a) ----
__device__ __forceinline__ u64 pack2(float lo, float hi) {
    u64 r; asm("mov.b64 %0, {%1, %2};" : "=l"(r) : "f"(lo), "f"(hi)); return r;
}
__device__ __forceinline__ void unpack2(u64 v, float& lo, float& hi) {
    asm("mov.b64 {%0, %1}, %2;" : "=f"(lo), "=f"(hi) : "l"(v));
}
__device__ __forceinline__ u64 fma2(u64 a, u64 b, u64 c) {
    u64 d; asm("fma.rn.f32x2 %0, %1, %2, %3;" : "=l"(d) : "l"(a), "l"(b), "l"(c)); return d;
}

// ============================================================================
// Kernel 1: projection partials. Grid (DSPLIT, 64 token-blocks) = 512 blocks.
// Block: 128 threads, 256 tokens (tid and tid+128). x staged through smem with
// COALESCED loads (full 128B lines -> 4 wavefronts/LDG vs 32 for the private-
// row pattern), scalar pitch-33 layout => inner reads xs[tid][k] conflict-free
// (bank = tid + k mod 32). W tile (32 x 36) restaged per 32-d tile.
// Inner mix per k: 2 LDS.32 + 8 LDS.128 + 1 LDS.64 + 2 MOV + 36 FFMA2.
// ============================================================================
__global__ __launch_bounds__(128)
void proj_kernel(const float* __restrict__ x,
                 const float* __restrict__ Wq,
                 const float* __restrict__ Wk,
                 const float* __restrict__ Ww)
{
    __shared__ float xs[256][33];   // 33.8 KB, pad 33: conflict-free reads
    __shared__ float ws[32][36];    //  4.6 KB

    const int tid   = threadIdx.x;
    const int dbase = blockIdx.x * DCHUNK;
    const int tok0  = blockIdx.y * 256;
    const int t0    = tok0 + tid;          // token A
    const int t1    = tok0 + tid + 128;    // token B

    u64 acc0[17], acc1[17];
    #pragma unroll
    for (int p = 0; p < 17; p++) { acc0[p] = 0ull; acc1[p] = 0ull; }

    const int wrow = tid >> 2;             // 0..31  (W staging)
    const int wq   = (tid & 3) * 4;        // 0,4,8,12

    #pragma unroll 1
    for (int dt = 0; dt < DCHUNK; dt += 32) {
        const int d0 = dbase + dt;
        __syncthreads();   // previous tile fully consumed

        // ---- stage x tile: 256 tokens x 32 d, coalesced LDG.128 ----
        // task = tid + 128*i ; row = task>>3 ; c4 = (task&7)*4
        // warp covers 4 full 128B lines per LDG. STS scalar: bank =
        // (l>>3) + 4*(l&7) + j mod 32 -> all 32 lanes distinct.
        #pragma unroll
        for (int i = 0; i < 16; i++) {
            int task = tid + 128 * i;
            int row  = task >> 3;
            int c4   = (task & 7) * 4;
            const float4 v = *reinterpret_cast<const float4*>(
                &x[(size_t)(tok0 + row) * DMODEL + d0 + c4]);
            xs[row][c4 + 0] = v.x;
            xs[row][c4 + 1] = v.y;
            xs[row][c4 + 2] = v.z;
            xs[row][c4 + 3] = v.w;
        }

        // ---- stage W tile: 32 x 36 ----
        {
            const float4 vq = *reinterpret_cast<const float4*>(
                &Wq[(size_t)(d0 + wrow) * 16 + wq]);
            ws[wrow][wq + 0] = vq.x; ws[wrow][wq + 1] = vq.y;
            ws[wrow][wq + 2] = vq.z; ws[wrow][wq + 3] = vq.w;
            const float4 vk = *reinterpret_cast<const float4*>(
                &Wk[(size_t)(d0 + wrow) * 16 + wq]);
            ws[wrow][16 + wq + 0] = vk.x; ws[wrow][16 + wq + 1] = vk.y;
            ws[wrow][16 + wq + 2] = vk.z; ws[wrow][16 + wq + 3] = vk.w;
            if (tid < 32) {
                ws[tid][32] = Ww[d0 + tid];
                ws[tid][33] = 0.f; ws[tid][34] = 0.f; ws[tid][35] = 0.f;
            }
        }
        __syncthreads();

        // ---- compute: 32 k-steps, 2 tokens/thread ----
        #pragma unroll 8
        for (int k = 0; k < 32; k++) {
            const float v0 = xs[tid][k];
            const float v1 = xs[tid + 128][k];
            const u64 xd0 = pack2(v0, v0);
            const u64 xd1 = pack2(v1, v1);
            #pragma unroll
            for (int q = 0; q < 8; q++) {
                const ulonglong2 wv =
                    *reinterpret_cast<const ulonglong2*>(&ws[k][4 * q]);
                acc0[2 * q]     = fma2(xd0, wv.x, acc0[2 * q]);
                acc0[2 * q + 1] = fma2(xd0, wv.y, acc0[2 * q + 1]);
                acc1[2 * q]     = fma2(xd1, wv.x, acc1[2 * q]);
                acc1[2 * q + 1] = fma2(xd1, wv.y, acc1[2 * q + 1]);
            }
            const u64 w16 = *reinterpret_cast<const u64*>(&ws[k][32]);
            acc0[16] = fma2(xd0, w16, acc0[16]);
            acc1[16] = fma2(xd1, w16, acc1[16]);
        }
    }

    // Write partials (bit patterns are the floats; no unpack needed)
    float* p0 = &g_part[((size_t)blockIdx.x * TOKENS + t0) * NCPAD];
    float* p1 = &g_part[((size_t)blockIdx.x * TOKENS + t1) * NCPAD];
    #pragma unroll
    for (int q = 0; q < 8; q++) {
        ulonglong2 v0; v0.x = acc0[2 * q]; v0.y = acc0[2 * q + 1];
        ulonglong2 v1; v1.x = acc1[2 * q]; v1.y = acc1[2 * q + 1];
        *reinterpret_cast<ulonglong2*>(&p0[4 * q]) = v0;
        *reinterpret_cast<ulonglong2*>(&p1[4 * q]) = v1;
    }
    *reinterpret_cast<u64*>(&p0[32]) = acc0[16];
    *reinterpret_cast<u64*>(&p1[32]) = acc1[16];
}

// ============================================================================
// Kernel 2: reduce D-split partials (float4-vectorized, 9 quads/token).
// ============================================================================
__global__ __launch_bounds__(256)
void reduce_kernel()
{
    int i = blockIdx.x * 256 + threadIdx.x;   // 0 .. 16384*9-1
    int tok = i / 9, c4 = i - tok * 9;
    float4 s = make_float4(0.f, 0.f, 0.f, 0.f);
    #pragma unroll
    for (int r = 0; r < DSPLIT; r++) {
        const float4 v = *reinterpret_cast<const float4*>(
            &g_part[((size_t)r * TOKENS + tok) * NCPAD + 4 * c4]);
        s.x += v.x; s.y += v.y; s.z += v.z; s.w += v.w;
    }
    if (c4 < 4)
        *reinterpret_cast<float4*>(&g_q[tok * 16 + 4 * c4]) = s;
    else if (c4 < 8)
        *reinterpret_cast<float4*>(&g_k[tok * 16 + 4 * (c4 - 4)]) = s;
    else
        g_w[tok] = s.x;
}

// ============================================================================
// Kernel 3: out[b,t,s] = relu(Q[b,t] . K[b,s]) * w[b,t]
// Grid (32 s-tiles, 32 t-tiles, 4) = 4096 blocks, 256 threads.
// Tile 128t x 128s, micro-tile 8t x 8s (s-pairs in f32x2).
// Per d: 2 LDS.128 (K, bank-swizzled) + 8 LDS.64 (Q dup) + 32 FFMA2.
// ============================================================================

// kt column swizzle: spreads the 32B-strided LDS.128 across all bank groups.
__device__ __forceinline__ int kt_col(int s) {
    int st = s >> 3;
    return 8 * st + 4 * (st >> 2) + (s & 7);
}

__global__ __launch_bounds__(256)
void dot_kernel(float* __restrict__ out)
{
    __shared__ u64   qs2[128][17];   // [t][d] value-duplicated pairs (17.4 KB)
    __shared__ float kt[16][148];    // [d][s] transposed, swizzled (9.5 KB)
    __shared__ float wts[128];

    const int tid = threadIdx.x;
    const int tt  = tid >> 4;        // 0..15 : t-thread
    const int st  = tid & 15;        // 0..15 : s-thread (8 s each)

    const int b     = blockIdx.z;
    const int tbase = blockIdx.y * 128;
    const int sbase = blockIdx.x * 128;
    const int tokq  = b * SEQ + tbase;
    const int tokk  = b * SEQ + sbase;

    // Stage Q tile duplicated: 128 rows x 16 -> u64 dup pairs
    #pragma unroll
    for (int i = 0; i < 2; i++) {
        int task = tid + 256 * i;
        int row = task >> 2, q = (task & 3) * 4;
        const float4 v = *reinterpret_cast<const float4*>(
            &g_q[(size_t)(tokq + row) * 16 + q]);
        qs2[row][q + 0] = pack2(v.x, v.x);
        qs2[row][q + 1] = pack2(v.y, v.y);
        qs2[row][q + 2] = pack2(v.z, v.z);
        qs2[row][q + 3] = pack2(v.w, v.w);
    }
    // Stage K transposed + swizzled: kt[d][col(s)] = K[s][d]
    #pragma unroll
    for (int i = 0; i < 2; i++) {
        int task = tid + 256 * i;
        int s = task >> 2, q = (task & 3) * 4;
        const float4 v = *reinterpret_cast<const float4*>(
            &g_k[(size_t)(tokk + s) * 16 + q]);
        const int c = kt_col(s);
        kt[q + 0][c] = v.x;
        kt[q + 1][c] = v.y;
        kt[q + 2][c] = v.z;
        kt[q + 3][c] = v.w;
    }
    if (tid < 128) wts[tid] = g_w[tokq + tid];
    __syncthreads();

    const int c0 = 8 * st + 4 * (st >> 2);   // this thread's kt column base

    u64 acc[8][4];
    #pragma unroll
    for (int i = 0; i < 8; i++)
        #pragma unroll
        for (int j = 0; j < 4; j++) acc[i][j] = 0ull;

    #pragma unroll
    for (int d = 0; d < 16; d++) {
        const ulonglong2 ka = *reinterpret_cast<const ulonglong2*>(&kt[d][c0]);
        const ulonglong2 kb = *reinterpret_cast<const ulonglong2*>(&kt[d][c0 + 4]);
        #pragma unroll
        for (int i = 0; i < 8; i++) {
            const u64 q2 = qs2[tt + 16 * i][d];
            acc[i][0] = fma2(q2, ka.x, acc[i][0]);
            acc[i][1] = fma2(q2, ka.y, acc[i][1]);
            acc[i][2] = fma2(q2, kb.x, acc[i][2]);
            acc[i][3] = fma2(q2, kb.y, acc[i][3]);
        }
    }

    // Epilogue: relu, * w[t], 2x STG.128 per row
    #pragma unroll
    for (int i = 0; i < 8; i++) {
        const int t = tbase + tt + 16 * i;
        const float wt = wts[tt + 16 * i];
        float lo, hi;
        float4 oa, ob;
        unpack2(acc[i][0], lo, hi);
        oa.x = fmaxf(lo, 0.f) * wt;  oa.y = fmaxf(hi, 0.f) * wt;
        unpack2(acc[i][1], lo, hi);
        oa.z = fmaxf(lo, 0.f) * wt;  oa.w = fmaxf(hi, 0.f) * wt;
        unpack2(acc[i][2], lo, hi);
        ob.x = fmaxf(lo, 0.f) * wt;  ob.y = fmaxf(hi, 0.f) * wt;
        unpack2(acc[i][3], lo, hi);
        ob.z = fmaxf(lo, 0.f) * wt;  ob.w = fmaxf(hi, 0.f) * wt;
        float* o = &out[((size_t)(b * SEQ + t)) * SEQ + sbase + st * 8];
        *reinterpret_cast<float4*>(o)     = oa;
        *reinterpret_cast<float4*>(o + 4) = ob;
    }
}

// ============================================================================
extern "C" void kernel_launch(void* const* d_in, const int* in_sizes, int n_in,
                              void* d_out, int out_size)
{
    const float* x  = (const float*)d_in[0];
    const float* Wq = (const float*)d_in[1];
    const float* Wk = (const float*)d_in[2];
    const float* Ww = (const float*)d_in[3];
    float* out = (float*)d_out;

    proj_kernel<<<dim3(DSPLIT, TOKENS / 256), 128>>>(x, Wq, Wk, Ww);
    reduce_kernel<<<(TOKENS * 9) / 256, 256>>>();
    dot_kernel<<<dim3(SEQ / 128, SEQ / 128, BATCH), 256>>>(out);
}

// round 12
// speedup vs baseline: 1.0073x; 1.0073x over previous
#include <cuda_runtime.h>
#include <cstdint>

// Problem constants
#define BATCH   4
#define SEQ     4096
#define DMODEL  2048
#define TOKENS  (BATCH * SEQ)     // 16384
#define NCPAD   36                // 16 q + 16 k + w + 3 pad (float4-aligned pitch)
#define DSPLIT  8
#define DCHUNK  (DMODEL / DSPLIT) // 256

typedef unsigned long long u64;

// Scratch (static device globals: no dynamic allocation allowed)
__device__ float g_part[(size_t)DSPLIT * TOKENS * NCPAD];   // ~18.9 MB
__device__ float g_q[TOKENS * 16];
__device__ float g_k[TOKENS * 16];
__device__ float g_w[TOKENS];

// ---- packed f32x2 helpers (FFMA2 path, PTX-only on sm_103a) ----
__device__ __forceinline__ u64 pack2(float lo, float hi) {
    u64 r; asm("mov.b64 %0, {%1, %2};" : "=l"(r) : "f"(lo), "f"(hi)); return r;
}
__device__ __forceinline__ void unpack2(u64 v, float& lo, float& hi) {
    asm("mov.b64 {%0, %1}, %2;" : "=f"(lo), "=f"(hi) : "l"(v));
}
__device__ __forceinline__ u64 fma2(u64 a, u64 b, u64 c) {
    u64 d; asm("fma.rn.f32x2 %0, %1, %2, %3;" : "=l"(d) : "l"(a), "l"(b), "l"(c)); return d;
}

// ============================================================================
// Kernel 1: projection partials. Grid (DSPLIT, 64) = 512 blocks, 128 threads,
// 2 tokens/thread (tid, tid+128). x flows GMEM->SMEM via cp.async (LDGSTS):
// zero register cost, fully coalesced 16B chunks, 2-tile-deep pipeline
// (8-d tiles, double-buffered smem). W chunk staged in two 128-row halves
// (re-staged at mid-chunk). Inner loop identical to the proven 76%-fma mix:
// per k: broadcast W row (8 LDS.128 + 1 LDS.64) + 34 FFMA2 for 2 tokens.
// __launch_bounds__(128,4): 4 blocks/SM, 64KB cp.async in flight per SM.
// ============================================================================
__global__ __launch_bounds__(128, 4)
void proj_kernel(const float* __restrict__ x,
                 const float* __restrict__ Wq,
                 const float* __restrict__ Wk,
                 const float* __restrict__ Ww)
{
    __shared__ float ws[128][36];        // 18.4 KB  (half of the D chunk)
    __shared__ float xs[2][256][12];     // 24.6 KB  (8-d tile, pitch 12: LDS.128
                                         //  at 12*tid -> conflict-free)

    const int tid   = threadIdx.x;
    const int dbase = blockIdx.x * DCHUNK;
    const int tok0  = blockIdx.y * 256;

    u64 acc0[17], acc1[17];
    #pragma unroll
    for (int p = 0; p < 17; p++) { acc0[p] = 0ull; acc1[p] = 0ull; }

    // ---- stage a 128-row half of W: one row per thread ----
    auto stage_w = [&](int d0) {
        const float4* wq = reinterpret_cast<const float4*>(&Wq[(size_t)(d0 + tid) * 16]);
        *reinterpret_cast<float4*>(&ws[tid][0])  = wq[0];
        *reinterpret_cast<float4*>(&ws[tid][4])  = wq[1];
        *reinterpret_cast<float4*>(&ws[tid][8])  = wq[2];
        *reinterpret_cast<float4*>(&ws[tid][12]) = wq[3];
        const float4* wk = reinterpret_cast<const float4*>(&Wk[(size_t)(d0 + tid) * 16]);
        *reinterpret_cast<float4*>(&ws[tid][16]) = wk[0];
        *reinterpret_cast<float4*>(&ws[tid][20]) = wk[1];
        *reinterpret_cast<float4*>(&ws[tid][24]) = wk[2];
        *reinterpret_cast<float4*>(&ws[tid][28]) = wk[3];
        ws[tid][32] = Ww[d0 + tid];
        ws[tid][33] = 0.f; ws[tid][34] = 0.f; ws[tid][35] = 0.f;
    };

    // ---- post one 8-d tile (256 tokens x 32B) as a cp.async group ----
    auto post_tile = [&](int t) {
        const int buf = t & 1;
        const int dt  = t * 8;
        #pragma unroll
        for (int i = 0; i < 4; i++) {
            const int task = tid + 128 * i;
            const int row  = task >> 1;
            const int c4   = (task & 1) * 4;
            const float* src = &x[(size_t)(tok0 + row) * DMODEL + dbase + dt + c4];
            const uint32_t dst =
                (uint32_t)__cvta_generic_to_shared(&xs[buf][row][c4]);
            asm volatile("cp.async.ca.shared.global [%0], [%1], 16;"
                         :: "r"(dst), "l"(src));
        }
        asm volatile("cp.async.commit_group;" ::: "memory");
    };

    stage_w(dbase);
    post_tile(0);
    post_tile(1);

    #pragma unroll 1
    for (int t = 0; t < 32; t++) {
        if (t == 16) stage_w(dbase + 128);   // prior sync: old half consumed

        if (t < 31) asm volatile("cp.async.wait_group 1;" ::: "memory");
        else        asm volatile("cp.async.wait_group 0;" ::: "memory");
        __syncthreads();

        const int buf   = t & 1;
        const int wbase = (t & 15) * 8;      // row within current W half

        float xa[8], xb[8];
        *reinterpret_cast<float4*>(&xa[0]) =
            *reinterpret_cast<const float4*>(&xs[buf][tid][0]);
        *reinterpret_cast<float4*>(&xa[4]) =
            *reinterpret_cast<const float4*>(&xs[buf][tid][4]);
        *reinterpret_cast<float4*>(&xb[0]) =
            *reinterpret_cast<const float4*>(&xs[buf][tid + 128][0]);
        *reinterpret_cast<float4*>(&xb[4]) =
            *reinterpret_cast<const float4*>(&xs[buf][tid + 128][4]);

        #pragma unroll
        for (int j = 0; j < 8; j++) {
            const u64 xd0 = pack2(xa[j], xa[j]);
            const u64 xd1 = pack2(xb[j], xb[j]);
            const int k = wbase + j;
            #pragma unroll
            for (int q = 0; q < 8; q++) {
                const ulonglong2 wv =
                    *reinterpret_cast<const ulonglong2*>(&ws[k][4 * q]);
                acc0[2 * q]     = fma2(xd0, wv.x, acc0[2 * q]);
                acc0[2 * q + 1] = fma2(xd0, wv.y, acc0[2 * q + 1]);
                acc1[2 * q]     = fma2(xd1, wv.x, acc1[2 * q]);
                acc1[2 * q + 1] = fma2(xd1, wv.y, acc1[2 * q + 1]);
            }
            const u64 w16 = *reinterpret_cast<const u64*>(&ws[k][32]);
            acc0[16] = fma2(xd0, w16, acc0[16]);
            acc1[16] = fma2(xd1, w16, acc1[16]);
        }

        __syncthreads();
        if (t < 30) post_tile(t + 2);
    }

    // Write partials (bit patterns are the floats; no unpack needed)
    float* p0 = &g_part[((size_t)blockIdx.x * TOKENS + tok0 + tid) * NCPAD];
    float* p1 = &g_part[((size_t)blockIdx.x * TOKENS + tok0 + tid + 128) * NCPAD];
    #pragma unroll
    for (int q = 0; q < 8; q++) {
        ulonglong2 v0; v0.x = acc0[2 * q]; v0.y = acc0[2 * q + 1];
        ulonglong2 v1; v1.x = acc1[2 * q]; v1.y = acc1[2 * q + 1];
        *reinterpret_cast<ulonglong2*>(&p0[4 * q]) = v0;
        *reinterpret_cast<ulonglong2*>(&p1[4 * q]) = v1;
    }
    *reinterpret_cast<u64*>(&p0[32]) = acc0[16];
    *reinterpret_cast<u64*>(&p1[32]) = acc1[16];
}

// ============================================================================
// Kernel 2: reduce D-split partials (float4-vectorized, 9 quads/token).
// ============================================================================
__global__ __launch_bounds__(256)
void reduce_kernel()
{
    int i = blockIdx.x * 256 + threadIdx.x;   // 0 .. 16384*9-1
    int tok = i / 9, c4 = i - tok * 9;
    float4 s = make_float4(0.f, 0.f, 0.f, 0.f);
    #pragma unroll
    for (int r = 0; r < DSPLIT; r++) {
        const float4 v = *reinterpret_cast<const float4*>(
            &g_part[((size_t)r * TOKENS + tok) * NCPAD + 4 * c4]);
        s.x += v.x; s.y += v.y; s.z += v.z; s.w += v.w;
    }
    if (c4 < 4)
        *reinterpret_cast<float4*>(&g_q[tok * 16 + 4 * c4]) = s;
    else if (c4 < 8)
        *reinterpret_cast<float4*>(&g_k[tok * 16 + 4 * (c4 - 4)]) = s;
    else
        g_w[tok] = s.x;
}

// ============================================================================
// Kernel 3: out[b,t,s] = relu(Q[b,t] . K[b,s]) * w[b,t]
// Grid (32 s-tiles, 32 t-tiles, 4) = 4096 blocks, 256 threads.
// Tile 128t x 128s, micro-tile 8t x 8s (s-pairs in f32x2).
// Per d: 2 LDS.128 (K, bank-swizzled) + 8 LDS.64 (Q dup) + 32 FFMA2.
// ============================================================================

// kt column swizzle: spreads the 32B-strided LDS.128 across all bank groups.
__device__ __forceinline__ int kt_col(int s) {
    int st = s >> 3;
    return 8 * st + 4 * (st >> 2) + (s & 7);
}

__global__ __launch_bounds__(256)
void dot_kernel(float* __restrict__ out)
{
    __shared__ u64   qs2[128][17];   // [t][d] value-duplicated pairs (17.4 KB)
    __shared__ float kt[16][148];    // [d][s] transposed, swizzled (9.5 KB)
    __shared__ float wts[128];

    const int tid = threadIdx.x;
    const int tt  = tid >> 4;        // 0..15 : t-thread
    const int st  = tid & 15;        // 0..15 : s-thread (8 s each)

    const int b     = blockIdx.z;
    const int tbase = blockIdx.y * 128;
    const int sbase = blockIdx.x * 128;
    const int tokq  = b * SEQ + tbase;
    const int tokk  = b * SEQ + sbase;

    // Stage Q tile duplicated: 128 rows x 16 -> u64 dup pairs
    #pragma unroll
    for (int i = 0; i < 2; i++) {
        int task = tid + 256 * i;
        int row = task >> 2, q = (task & 3) * 4;
        const float4 v = *reinterpret_cast<const float4*>(
            &g_q[(size_t)(tokq + row) * 16 + q]);
        qs2[row][q + 0] = pack2(v.x, v.x);
        qs2[row][q + 1] = pack2(v.y, v.y);
        qs2[row][q + 2] = pack2(v.z, v.z);
        qs2[row][q + 3] = pack2(v.w, v.w);
    }
    // Stage K transposed + swizzled: kt[d][col(s)] = K[s][d]
    #pragma unroll
    for (int i = 0; i < 2; i++) {
        int task = tid + 256 * i;
        int s = task >> 2, q = (task & 3) * 4;
        const float4 v = *reinterpret_cast<const float4*>(
            &g_k[(size_t)(tokk + s) * 16 + q]);
        const int c = kt_col(s);
        kt[q + 0][c] = v.x;
        kt[q + 1][c] = v.y;
        kt[q + 2][c] = v.z;
        kt[q + 3][c] = v.w;
    }
    if (tid < 128) wts[tid] = g_w[tokq + tid];
    __syncthreads();

    const int c0 = 8 * st + 4 * (st >> 2);   // this thread's kt column base

    u64 acc[8][4];
    #pragma unroll
    for (int i = 0; i < 8; i++)
        #pragma unroll
        for (int j = 0; j < 4; j++) acc[i][j] = 0ull;

    #pragma unroll
    for (int d = 0; d < 16; d++) {
        const ulonglong2 ka = *reinterpret_cast<const ulonglong2*>(&kt[d][c0]);
        const ulonglong2 kb = *reinterpret_cast<const ulonglong2*>(&kt[d][c0 + 4]);
        #pragma unroll
        for (int i = 0; i < 8; i++) {
            const u64 q2 = qs2[tt + 16 * i][d];
            acc[i][0] = fma2(q2, ka.x, acc[i][0]);
            acc[i][1] = fma2(q2, ka.y, acc[i][1]);
            acc[i][2] = fma2(q2, kb.x, acc[i][2]);
            acc[i][3] = fma2(q2, kb.y, acc[i][3]);
        }
    }

    // Epilogue: relu, * w[t], 2x STG.128 per row
    #pragma unroll
    for (int i = 0; i < 8; i++) {
        const int t = tbase + tt + 16 * i;
        const float wt = wts[tt + 16 * i];
        float lo, hi;
        float4 oa, ob;
        unpack2(acc[i][0], lo, hi);
        oa.x = fmaxf(lo, 0.f) * wt;  oa.y = fmaxf(hi, 0.f) * wt;
        unpack2(acc[i][1], lo, hi);
        oa.z = fmaxf(lo, 0.f) * wt;  oa.w = fmaxf(hi, 0.f) * wt;
        unpack2(acc[i][2], lo, hi);
        ob.x = fmaxf(lo, 0.f) * wt;  ob.y = fmaxf(hi, 0.f) * wt;
        unpack2(acc[i][3], lo, hi);
        ob.z = fmaxf(lo, 0.f) * wt;  ob.w = fmaxf(hi, 0.f) * wt;
        float* o = &out[((size_t)(b * SEQ + t)) * SEQ + sbase + st * 8];
        *reinterpret_cast<float4*>(o)     = oa;
        *reinterpret_cast<float4*>(o + 4) = ob;
    }
}

// ============================================================================
extern "C" void kernel_launch(void* const* d_in, const int* in_sizes, int n_in,
                              void* d_out, int out_size)
{
    const float* x  = (const float*)d_in[0];
    const float* Wq = (const float*)d_in[1];
    const float* Wk = (const float*)d_in[2];
    const float* Ww = (const float*)d_in[3];
    float* out = (float*)d_out;

    proj_kernel<<<dim3(DSPLIT, TOKENS / 256), 128>>>(x, Wq, Wk, Ww);
    reduce_kernel<<<(TOKENS * 9) / 256, 256>>>();
    dot_kernel<<<dim3(SEQ / 128, SEQ / 128, BATCH), 256>>>(out);
}